// round 3
// baseline (speedup 1.0000x reference)
#include <cuda_runtime.h>

// Problem constants
#define S_STEPS 15
#define NETW 16
#define NCH 16
#define HW 4096            // 64*64
#define NPIX (64 * 4096)   // B*H*W = 262144
#define NPAIR (NPIX / 2)   // 131072 (two pixels per thread, packed f32x2)
#define HALF_LOG_2PI 0.918938533204672741780329736406f

typedef unsigned long long ull;

union F2U { ull u; float2 f; };
__device__ __forceinline__ ull f2u(float2 f) { F2U t; t.f = f; return t.u; }
__device__ __forceinline__ float2 u2f(ull u) { F2U t; t.u = u; return t.f; }

// Packed dual-FMA: 2 fp32 FMAs per instruction on the fma pipe (sm_10x).
__device__ __forceinline__ ull ffma2(ull a, ull b, ull c) {
    ull d;
    asm("fma.rn.f32x2 %0, %1, %2, %3;" : "=l"(d) : "l"(a), "l"(b), "l"(c));
    return d;
}

__device__ __forceinline__ ull relu2(ull a) {
    float2 f = u2f(a);
    return f2u(make_float2(fmaxf(f.x, 0.f), fmaxf(f.y, 0.f)));
}

// Launch-constant parameters of the first-channel head (input is zeros):
// [0] = loc1, [1] = exp(-log_scale1), [2] = -log_scale1 - 0.5*log(2*pi)
__device__ float g_c1[3];

__global__ void precompute_kernel(const float* __restrict__ n1_b1,
                                  const float* __restrict__ n1_w2,
                                  const float* __restrict__ n1_b2,
                                  const float* __restrict__ n1_w3,
                                  const float* __restrict__ n1_b3) {
    if (threadIdx.x == 0) {
        float h1[NETW], h2[NETW];
        #pragma unroll
        for (int i = 0; i < NETW; i++) h1[i] = fmaxf(n1_b1[i], 0.f);
        #pragma unroll
        for (int o = 0; o < NETW; o++) {
            float a = n1_b2[o];
            #pragma unroll
            for (int p = 0; p < NETW; p++) a += n1_w2[o * NETW + p] * h1[p];
            h2[o] = fmaxf(a, 0.f);
        }
        float loc = n1_b3[0], ls = n1_b3[1];
        #pragma unroll
        for (int p = 0; p < NETW; p++) {
            loc += n1_w3[p] * h2[p];
            ls  += n1_w3[NETW + p] * h2[p];
        }
        g_c1[0] = loc;
        g_c1[1] = expf(-ls);
        g_c1[2] = -ls - HALF_LOG_2PI;
    }
}

// Shared memory layout (units = float2; weights duplicated (w,w) so the FFMA2
// multiplier operand comes straight from an LDS with no pack MOV).
#define SW1_OFF 0
#define SW2_OFF (S_STEPS * 256)
#define SW3_OFF (2 * S_STEPS * 256)
#define SB1_OFF (SW3_OFF + S_STEPS * 32)
#define SB2_OFF (SB1_OFF + S_STEPS * 16)
#define SB3_OFF (SB2_OFF + S_STEPS * 16)
#define SM_F2_TOT (SB3_OFF + S_STEPS * 2)
#define SM_BYTES (SM_F2_TOT * 8)   // 69360 bytes

__global__ __launch_bounds__(256) void spatial_nn_kernel(
    const float* __restrict__ samples,
    const float* __restrict__ w1, const float* __restrict__ b1,
    const float* __restrict__ w2, const float* __restrict__ b2,
    const float* __restrict__ w3, const float* __restrict__ b3,
    float* __restrict__ out) {
    extern __shared__ float2 sm[];
    const int tid = threadIdx.x;

    // Stage duplicated weights into shared memory (broadcast reads later).
    for (int i = tid; i < S_STEPS * 256; i += 256) { float v = w1[i]; sm[SW1_OFF + i] = make_float2(v, v); }
    for (int i = tid; i < S_STEPS * 256; i += 256) { float v = w2[i]; sm[SW2_OFF + i] = make_float2(v, v); }
    for (int i = tid; i < S_STEPS * 32;  i += 256) { float v = w3[i]; sm[SW3_OFF + i] = make_float2(v, v); }
    for (int i = tid; i < S_STEPS * 16;  i += 256) { float v = b1[i]; sm[SB1_OFF + i] = make_float2(v, v); }
    for (int i = tid; i < S_STEPS * 16;  i += 256) { float v = b2[i]; sm[SB2_OFF + i] = make_float2(v, v); }
    for (int i = tid; i < S_STEPS * 2;   i += 256) { float v = b3[i]; sm[SB3_OFF + i] = make_float2(v, v); }
    __syncthreads();

    const int t = blockIdx.x * 256 + tid;   // pair index
    const int pix = t * 2;                  // even pixel of the pair
    const int b = pix >> 12;                // / (H*W)
    const int hw = pix & 4095;              // % (H*W)
    const float* sp = samples + ((size_t)b * NCH) * HW + hw;

    // Load all 16 channels for both pixels (float2 = 2 adjacent W positions).
    ull xv[NCH];
    #pragma unroll
    for (int c = 0; c < NCH; c++)
        xv[c] = f2u(*reinterpret_cast<const float2*>(sp + c * HW));

    // First-channel log-prob from the precomputed constants.
    const float loc1 = g_c1[0], inv1 = g_c1[1], c1 = g_c1[2];
    float2 x0 = u2f(xv[0]);
    float z0 = (x0.x - loc1) * inv1;
    float z1 = (x0.y - loc1) * inv1;
    float lp_lo = -0.5f * z0 * z0 + c1;
    float lp_hi = -0.5f * z1 * z1 + c1;

    for (int s = 0; s < S_STEPS; s++) {
        const float2* w1p = sm + SW1_OFF + s * 256;
        const float2* w2p = sm + SW2_OFF + s * 256;
        const float2* w3p = sm + SW3_OFF + s * 32;
        const float2* b1p = sm + SB1_OFF + s * 16;
        const float2* b2p = sm + SB2_OFF + s * 16;
        const float2* b3p = sm + SB3_OFF + s * 2;

        ull h1[NETW];
        #pragma unroll
        for (int o = 0; o < NETW; o++) {
            ull acc = f2u(b1p[o]);
            #pragma unroll
            for (int c = 0; c < NCH; c++)
                acc = ffma2(f2u(w1p[o * NCH + c]), xv[c], acc);
            h1[o] = relu2(acc);
        }

        ull h2[NETW];
        #pragma unroll
        for (int o = 0; o < NETW; o++) {
            ull acc = f2u(b2p[o]);
            #pragma unroll
            for (int p = 0; p < NETW; p++)
                acc = ffma2(f2u(w2p[o * NETW + p]), h1[p], acc);
            h2[o] = relu2(acc);
        }

        ull accL = f2u(b3p[0]);
        ull accS = f2u(b3p[1]);
        #pragma unroll
        for (int p = 0; p < NETW; p++) {
            accL = ffma2(f2u(w3p[p]), h2[p], accL);
            accS = ffma2(f2u(w3p[NETW + p]), h2[p], accS);
        }

        float2 loc = u2f(accL);
        float2 ls  = u2f(accS);
        float2 xs  = u2f(xv[s + 1]);
        float ea = __expf(-ls.x);
        float eb = __expf(-ls.y);
        float za = (xs.x - loc.x) * ea;
        float zb = (xs.y - loc.y) * eb;
        lp_lo += -0.5f * za * za - ls.x - HALF_LOG_2PI;
        lp_hi += -0.5f * zb * zb - ls.y - HALF_LOG_2PI;
    }

    *reinterpret_cast<float2*>(out + pix) = make_float2(lp_lo, lp_hi);
}

extern "C" void kernel_launch(void* const* d_in, const int* in_sizes, int n_in,
                              void* d_out, int out_size) {
    const float* samples = (const float*)d_in[0];
    // d_in[1] = n1_w1 (unused: multiplies a zeros input)
    const float* n1_b1 = (const float*)d_in[2];
    const float* n1_w2 = (const float*)d_in[3];
    const float* n1_b2 = (const float*)d_in[4];
    const float* n1_w3 = (const float*)d_in[5];
    const float* n1_b3 = (const float*)d_in[6];
    const float* w1 = (const float*)d_in[7];
    const float* b1 = (const float*)d_in[8];
    const float* w2 = (const float*)d_in[9];
    const float* b2 = (const float*)d_in[10];
    const float* w3 = (const float*)d_in[11];
    const float* b3 = (const float*)d_in[12];
    float* out = (float*)d_out;

    // Opt in to >48KB dynamic shared memory (idempotent; skip if already set
    // so the graph-capture call performs no attribute mutation).
    cudaFuncAttributes attr;
    cudaFuncGetAttributes(&attr, spatial_nn_kernel);
    if (attr.maxDynamicSharedSizeBytes < SM_BYTES) {
        cudaFuncSetAttribute(spatial_nn_kernel,
                             cudaFuncAttributeMaxDynamicSharedMemorySize, SM_BYTES);
    }

    precompute_kernel<<<1, 32>>>(n1_b1, n1_w2, n1_b2, n1_w3, n1_b3);
    spatial_nn_kernel<<<NPAIR / 256, 256, SM_BYTES>>>(
        samples, w1, b1, w2, b2, w3, b3, out);
}